// round 17
// baseline (speedup 1.0000x reference)
#include <cuda_runtime.h>

#define BINS  10
#define BLOCK 256
#define OCC   6
#define GRID  (148 * OCC)

// Global scratch (zero at module load; reset by last block each run -> graph-replayable).
__device__ float    g_sum[BINS];
__device__ float    g_cnt[BINS];
__device__ unsigned g_ticket;

#define LOG2E 1.4426950408889634f
#define LN2   0.69314718055994531f
#define KBIG  4096.0f            // count embedded as multiples of 4096 in the same float
#define KINV  (1.0f / 4096.0f)

__device__ __forceinline__ float ex2_approx(float x) {
    float r; asm("ex2.approx.f32 %0, %1;" : "=f"(r) : "f"(x)); return r;   // MUFU.EX2
}
__device__ __forceinline__ float lg2_approx(float x) {
    float r; asm("lg2.approx.f32 %0, %1;" : "=f"(r) : "f"(x)); return r;   // MUFU.LG2
}
__device__ __forceinline__ float rcp_approx(float x) {
    float r; asm("rcp.approx.f32 %0, %1;" : "=f"(r) : "f"(x)); return r;   // MUFU.RCP
}

__shared__ float rows[BINS][BLOCK];    // [bin][tid]; S = 4096*cnt + sum(log2 p)
                                       // bank = tid mod 32 -> conflict-free for any bin

// Direct 2D shared indexing: guaranteed LDS/STS.
__device__ __forceinline__ void ghm_elem(float xx, int tt, int tid) {
    // z = x if t==0 else -x: sign-bit flip via single XOR.
    const int   zi = __float_as_int(xx) ^ (tt << 31);
    const float z  = __int_as_float(zi);
    const float a  = ex2_approx(z * LOG2E);       // e^z      (FMUL + MUFU.EX2)
    const float p  = 1.0f + a;                    // 1 + e^z  (inf-safe)
    const float l  = lg2_approx(p);               // ce = ln2 * l (scaled at finalize)
    const float r  = rcp_approx(p);               // sigmoid(z) = 1 - r
    const float g9 = 9.9999f - 9.9999f * r;       // FFMA: g*(BINS-1e-4) in [0, 9.9999)
    const int  bin = (int)g9;                     // F2I trunc; p=inf -> r=0 -> bin 9
    rows[bin][tid] += (l + KBIG);                 // LDS.32 + 2 FADD + STS.32
}

__global__ void __launch_bounds__(BLOCK, OCC)
ghm_fused(const float* __restrict__ x, const int* __restrict__ tg, int n,
          float* __restrict__ out, int out_size) {
    __shared__ float sh_fin[2 * BINS];
    __shared__ bool  s_last;

    const int tid = threadIdx.x;
    #pragma unroll
    for (int b = 0; b < BINS; ++b) rows[b][tid] = 0.0f;

    const int n4 = n >> 2;
    constexpr int stride4 = GRID * BLOCK;     // compile-time: [R+imm] addressing
    constexpr int per_it  = 2 * stride4;      // 8 elems/thread per iteration
    const int idx  = blockIdx.x * BLOCK + tid;
    const int full = n4 / per_it;             // fully-valid iterations (uniform)
    const float4* __restrict__ x4 = (const float4*)x;
    const int4*   __restrict__ t4 = (const int4*)tg;

    // Hot loop: front-batch 4 LDG.128, consume 8 elems. Latency hidden by
    // 12 warps/SMSP (OCC 6), not by per-warp double buffering (reg budget 40).
    for (int it = 0; it < full; ++it) {
        const int base = idx + it * per_it;
        const float4 x0 = __ldcs(&x4[base]);
        const float4 x1 = __ldcs(&x4[base + stride4]);
        const int4   t0 = __ldcs(&t4[base]);
        const int4   t1 = __ldcs(&t4[base + stride4]);
        ghm_elem(x0.x, t0.x, tid); ghm_elem(x0.y, t0.y, tid);
        ghm_elem(x0.z, t0.z, tid); ghm_elem(x0.w, t0.w, tid);
        ghm_elem(x1.x, t1.x, tid); ghm_elem(x1.y, t1.y, tid);
        ghm_elem(x1.z, t1.z, tid); ghm_elem(x1.w, t1.w, tid);
    }

    // Ragged float4 tail.
    for (int i = idx + full * per_it; i < n4; i += stride4) {
        const float4 xv = __ldcs(&x4[i]);
        const int4   tv = __ldcs(&t4[i]);
        ghm_elem(xv.x, tv.x, tid);
        ghm_elem(xv.y, tv.y, tid);
        ghm_elem(xv.z, tv.z, tid);
        ghm_elem(xv.w, tv.w, tid);
    }

    // Scalar tail (n % 4), block 0 only.
    if (blockIdx.x == 0 && tid < (n & 3)) {
        const int i = (n & ~3) + tid;
        ghm_elem(x[i], tg[i], tid);
    }

    // ── Split S = 4096*cnt + sum(l); reduce: warp butterfly -> block -> global ──
    float sums[BINS], cnts[BINS];
    #pragma unroll
    for (int b = 0; b < BINS; ++b) {
        const float S = rows[b][tid];      // own cell only; no sync needed
        const float c = rintf(S * KINV);   // count (sum(l) per thread-bin < 2048)
        cnts[b] = c;
        sums[b] = S - c * KBIG;            // sum of log2(p)
    }
    #pragma unroll
    for (int b = 0; b < BINS; ++b) {
        #pragma unroll
        for (int o = 16; o; o >>= 1) {
            sums[b] += __shfl_xor_sync(0xffffffffu, sums[b], o);
            cnts[b] += __shfl_xor_sync(0xffffffffu, cnts[b], o);
        }
    }
    if (tid < 2 * BINS) sh_fin[tid] = 0.0f;
    __syncthreads();
    if ((tid & 31) == 0) {
        #pragma unroll
        for (int b = 0; b < BINS; ++b) {
            atomicAdd(&sh_fin[b], sums[b]);
            atomicAdd(&sh_fin[BINS + b], cnts[b]);
        }
    }
    __syncthreads();
    if (tid < BINS) {
        atomicAdd(&g_sum[tid], sh_fin[tid]);
        atomicAdd(&g_cnt[tid], sh_fin[BINS + tid]);
    }

    // Last-block ticket: finalize + reset scratch for next graph replay.
    __threadfence();
    if (tid == 0) {
        const unsigned t = atomicAdd(&g_ticket, 1u);
        s_last = (t == (unsigned)(GRID - 1));
    }
    __syncthreads();
    if (s_last && tid < 32) {
        float c = 0.0f, ssum = 0.0f;
        if (tid < BINS) {
            c    = atomicAdd(&g_cnt[tid], 0.0f);   // coherent L2 read
            ssum = atomicAdd(&g_sum[tid], 0.0f);
        }
        const unsigned ne = __ballot_sync(0xffffffffu, (tid < BINS) && (c > 0.5f));
        const float nonempty = (float)__popc(ne);
        float term = 0.0f;
        if (tid < BINS)
            term = (LN2 * ssum) / fmaxf(c * nonempty, 1e-6f);  // deferred ln2 scale
        #pragma unroll
        for (int o = 16; o; o >>= 1)
            term += __shfl_xor_sync(0xffffffffu, term, o);
        for (int i = tid; i < out_size; i += 32) out[i] = term;
        if (tid < BINS) { g_sum[tid] = 0.0f; g_cnt[tid] = 0.0f; }
        if (tid == 0) g_ticket = 0u;
    }
}

extern "C" void kernel_launch(void* const* d_in, const int* in_sizes, int n_in,
                              void* d_out, int out_size) {
    const float* x = (const float*)d_in[0];
    const int*   t = (const int*)d_in[1];
    const int n = in_sizes[0];
    ghm_fused<<<GRID, BLOCK>>>(x, t, n, (float*)d_out, out_size);
}